// round 8
// baseline (speedup 1.0000x reference)
#include <cuda_runtime.h>
#include <cuda_fp16.h>
#include <cstdint>

#define SZ    4096
#define MTOT  8192
#define BM    128
#define BN    256
#define BK    64
#define KIT   (SZ / BK)          // 64 k-steps
#define NTHR  256                // 8 warps: 2m x 4n, warp tile 64x64
#define NSTG  4                  // cp.async pipeline stages

// device scratch (no allocation allowed in kernel_launch)
__device__ __half g_Xh[(size_t)MTOT * SZ];   // x in fp16, row-major [M][K]
__device__ __half g_Gt[(size_t)SZ * SZ];     // Gt[n][k] = G[k][n], fp16, K-major

// ---------------------------------------------------------------------------
// helpers (base-PTX only: cp.async / ldmatrix / mma.sync)
// ---------------------------------------------------------------------------
__device__ __forceinline__ uint32_t smem_u32(const void* p) {
    uint32_t a;
    asm("{ .reg .u64 t; cvta.to.shared.u64 t, %1; cvt.u32.u64 %0, t; }"
        : "=r"(a) : "l"(p));
    return a;
}
__device__ __forceinline__ uint32_t swz128(uint32_t off) {
    return off ^ ((off >> 3) & 0x70);        // SW128: conflict-free 128B-row tiles
}
__device__ __forceinline__ void cp16(uint32_t sdst, const void* gsrc) {
    asm volatile("cp.async.cg.shared.global [%0], [%1], 16;" :: "r"(sdst), "l"(gsrc));
}
__device__ __forceinline__ void ldsm_x4(uint32_t& r0, uint32_t& r1, uint32_t& r2,
                                        uint32_t& r3, uint32_t addr) {
    asm volatile("ldmatrix.sync.aligned.m8n8.x4.shared.b16 {%0,%1,%2,%3}, [%4];"
                 : "=r"(r0), "=r"(r1), "=r"(r2), "=r"(r3) : "r"(addr));
}
__device__ __forceinline__ void mma16816(float* c, uint32_t a0, uint32_t a1,
                                         uint32_t a2, uint32_t a3,
                                         uint32_t b0, uint32_t b1) {
    asm volatile(
        "mma.sync.aligned.m16n8k16.row.col.f32.f16.f16.f32 "
        "{%0,%1,%2,%3}, {%4,%5,%6,%7}, {%8,%9}, {%0,%1,%2,%3};"
        : "+f"(c[0]), "+f"(c[1]), "+f"(c[2]), "+f"(c[3])
        : "r"(a0), "r"(a1), "r"(a2), "r"(a3), "r"(b0), "r"(b1));
}

// ---------------------------------------------------------------------------
// Kernel 1 (fused prelude): blocks [0, 32768) convert x fp32->fp16,
// blocks [32768, 33024) build Gt. The two phases are independent (disjoint
// outputs) and co-schedule across the SM pool: convert is HBM-bound, build is
// FMA-bound, so fusing recovers the ~14us the serialized build_gt cost.
// ---------------------------------------------------------------------------
#define CONV_BLOCKS ((int)((size_t)MTOT * SZ / 4 / 256))   // 32768

__global__ void __launch_bounds__(256)
k_prelude(const float4* __restrict__ x,
          const float* __restrict__ core0, const float* __restrict__ core1,
          const float* __restrict__ core2) {
    if (blockIdx.x < CONV_BLOCKS) {
        // ---- phase A: x fp32 -> fp16 ----
        size_t i = (size_t)blockIdx.x * 256 + threadIdx.x;   // over float4
        float4 v = x[i];
        __half2* o = reinterpret_cast<__half2*>(g_Xh) + 2 * i;
        o[0] = __floats2half2_rn(v.x, v.y);
        o[1] = __floats2half2_rn(v.z, v.w);
        return;
    }
    // ---- phase B: build Gt[n][k] = G[k][n] ----
    //  G[k, y*256 + x1*16 + x2] = sum_c C2[(k*16+x2)*8+c] *
    //                             sum_b C1[((k*16+x1)*8+c)*8+b] * G0[(k*16+y)*8+b]
    const int bi = blockIdx.x - CONV_BLOCKS;     // 0..255
    const int x1 = bi >> 4;                      // 0..15
    const int k  = (bi & 15) * 256 + threadIdx.x;

    float c1r[64];  // C1[k, x1, c, b]
    const float4* c1p = reinterpret_cast<const float4*>(core1 + ((size_t)k * 16 + x1) * 64);
#pragma unroll
    for (int i = 0; i < 16; i++) {
        float4 v = c1p[i];
        c1r[4 * i] = v.x; c1r[4 * i + 1] = v.y; c1r[4 * i + 2] = v.z; c1r[4 * i + 3] = v.w;
    }
#pragma unroll
    for (int yc = 0; yc < 4; yc++) {
        float M[4][8];
#pragma unroll
        for (int yy = 0; yy < 4; yy++) {
            const int y = yc * 4 + yy;
            const float4* gp = reinterpret_cast<const float4*>(core0 + ((size_t)k * 16 + y) * 8);
            float4 a = gp[0], b = gp[1];
            float g0[8] = {a.x, a.y, a.z, a.w, b.x, b.y, b.z, b.w};
#pragma unroll
            for (int c = 0; c < 8; c++) {
                float s = 0.f;
#pragma unroll
                for (int bb = 0; bb < 8; bb++) s = fmaf(c1r[c * 8 + bb], g0[bb], s);
                M[yy][c] = s;
            }
        }
#pragma unroll
        for (int x2 = 0; x2 < 16; x2++) {
            const float4* cp = reinterpret_cast<const float4*>(core2 + ((size_t)k * 16 + x2) * 8);
            float4 a = cp[0], b = cp[1];
            float c2v[8] = {a.x, a.y, a.z, a.w, b.x, b.y, b.z, b.w};
#pragma unroll
            for (int yy = 0; yy < 4; yy++) {
                float s = 0.f;
#pragma unroll
                for (int c = 0; c < 8; c++) s = fmaf(c2v[c], M[yy][c], s);
                const int n = (yc * 4 + yy) * 256 + x1 * 16 + x2;
                g_Gt[(size_t)n * SZ + k] = __float2half_rn(s);
            }
        }
    }
}

// ---------------------------------------------------------------------------
// Kernel 2: GEMM out[m][n] = sum_k Xh[m][k] * Gt[n][k] + bias[n]
// 8 warps, warp grid 2m x 4n, warp tile 64x64. 4-stage cp.async pipeline
// (prefetch distance 3, wait_group 2) to shrink per-k-step latency bubbles.
// ---------------------------------------------------------------------------
#define A_BYTES  (BM * BK * 2)                    // 16384 per stage
#define B_BYTES  (BN * BK * 2)                    // 32768 per stage
#define SM_A     0
#define SM_B     (NSTG * A_BYTES)                 // 65536
#define SM_BIAS  (SM_B + NSTG * B_BYTES)          // 196608
#define SM_TOTAL (SM_BIAS + BN * 4)               // 197632

__global__ void __launch_bounds__(NTHR, 1)
k_gemm(const float* __restrict__ bias, float* __restrict__ out) {
    extern __shared__ char smem[];
    const uint32_t sb = smem_u32(smem);
    const int tid  = threadIdx.x;
    const int lane = tid & 31;
    const int wid  = tid >> 5;
    const int wm   = wid & 1;            // 2 m-warps x 64 rows
    const int wn   = wid >> 1;           // 4 n-warps x 64 cols
    const int m0 = blockIdx.y * BM;
    const int n0 = blockIdx.x * BN;

    float* sbias = reinterpret_cast<float*>(smem + SM_BIAS);
    sbias[tid] = bias[n0 + tid];

    // ---- loader: one full (A,B) k-stage; 256 threads, 16B per cp ----
    const int chunk = tid & 7;           // 16B chunk within 128B row
    const int rbase = tid >> 3;          // 0..31
    auto load_stage = [&](int ks, int stage) {
        const int k0 = ks * BK;
        const uint32_t ab = sb + SM_A + stage * A_BYTES;
        const uint32_t bb = sb + SM_B + stage * B_BYTES;
        const __half* ag = g_Xh + (size_t)(m0 + rbase) * SZ + k0 + chunk * 8;
        const __half* bg = g_Gt + (size_t)(n0 + rbase) * SZ + k0 + chunk * 8;
#pragma unroll
        for (int it = 0; it < 4; it++) {   // A: 128 rows
            const int r = rbase + 32 * it;
            cp16(ab + swz128((uint32_t)(r * 128 + chunk * 16)), ag + (size_t)(32 * it) * SZ);
        }
#pragma unroll
        for (int it = 0; it < 8; it++) {   // B: 256 rows
            const int r = rbase + 32 * it;
            cp16(bb + swz128((uint32_t)(r * 128 + chunk * 16)), bg + (size_t)(32 * it) * SZ);
        }
        asm volatile("cp.async.commit_group;" ::: "memory");
    };

    float acc[4][8][4];
#pragma unroll
    for (int mt = 0; mt < 4; mt++)
#pragma unroll
        for (int nt = 0; nt < 8; nt++)
#pragma unroll
            for (int j = 0; j < 4; j++) acc[mt][nt][j] = 0.f;

    load_stage(0, 0);
    load_stage(1, 1);
    load_stage(2, 2);

    // lane pieces for ldmatrix addressing
    const int g = lane >> 3;                                   // 0..3
    const int arow_off = ((lane >> 3) & 1) * 8 + (lane & 7);   // A row within 16
    const int acol_off = (lane >> 4) << 4;                     // A col byte (0/16)
    const int brow_off = ((g & 2) << 2) + (lane & 7);          // B row within 16
    const int bcol_off = (g & 1) << 4;                         // B col byte (0/16)

    for (int ks = 0; ks < KIT; ks++) {
        asm volatile("cp.async.wait_group 2;" ::: "memory");
        __syncthreads();
        if (ks + 3 < KIT) load_stage(ks + 3, (ks + 3) % NSTG);
        else              asm volatile("cp.async.commit_group;" ::: "memory");

        const uint32_t ab = sb + SM_A + (ks % NSTG) * A_BYTES;
        const uint32_t bb = sb + SM_B + (ks % NSTG) * B_BYTES;
#pragma unroll
        for (int k16 = 0; k16 < 4; k16++) {
            uint32_t a[4][4];
#pragma unroll
            for (int mt = 0; mt < 4; mt++) {
                const int row = wm * 64 + mt * 16 + arow_off;
                const int colb = k16 * 32 + acol_off;
                ldsm_x4(a[mt][0], a[mt][1], a[mt][2], a[mt][3],
                        ab + swz128((uint32_t)(row * 128 + colb)));
            }
            uint32_t b[8][2];
#pragma unroll
            for (int np = 0; np < 4; np++) {
                const int row = wn * 64 + np * 16 + brow_off;
                const int colb = k16 * 32 + bcol_off;
                uint32_t r0, r1, r2, r3;
                ldsm_x4(r0, r1, r2, r3, bb + swz128((uint32_t)(row * 128 + colb)));
                b[2 * np][0] = r0; b[2 * np][1] = r1;
                b[2 * np + 1][0] = r2; b[2 * np + 1][1] = r3;
            }
#pragma unroll
            for (int mt = 0; mt < 4; mt++)
#pragma unroll
                for (int nt = 0; nt < 8; nt++)
                    mma16816(acc[mt][nt], a[mt][0], a[mt][1], a[mt][2], a[mt][3],
                             b[nt][0], b[nt][1]);
        }
    }

    // ---- epilogue ----
    const int crow = lane >> 2;
    const int ccol = (lane & 3) * 2;
#pragma unroll
    for (int mt = 0; mt < 4; mt++) {
        const int m = m0 + wm * 64 + mt * 16 + crow;
#pragma unroll
        for (int nt = 0; nt < 8; nt++) {
            const int nc = wn * 64 + nt * 8 + ccol;
            float2 v0, v1;
            v0.x = acc[mt][nt][0] + sbias[nc];
            v0.y = acc[mt][nt][1] + sbias[nc + 1];
            v1.x = acc[mt][nt][2] + sbias[nc];
            v1.y = acc[mt][nt][3] + sbias[nc + 1];
            *reinterpret_cast<float2*>(out + (size_t)m * SZ + n0 + nc)       = v0;
            *reinterpret_cast<float2*>(out + (size_t)(m + 8) * SZ + n0 + nc) = v1;
        }
    }
}

// ---------------------------------------------------------------------------
extern "C" void kernel_launch(void* const* d_in, const int* in_sizes, int n_in,
                              void* d_out, int out_size) {
    const float* x     = (const float*)d_in[0];
    const float* core0 = (const float*)d_in[1];
    const float* core1 = (const float*)d_in[2];
    const float* core2 = (const float*)d_in[3];
    const float* bias  = (const float*)d_in[4];
    float* out = (float*)d_out;

    static bool attr_set = false;
    if (!attr_set) {
        cudaFuncSetAttribute(k_gemm, cudaFuncAttributeMaxDynamicSharedMemorySize, SM_TOTAL);
        attr_set = true;
    }

    k_prelude<<<CONV_BLOCKS + 256, 256>>>(
        reinterpret_cast<const float4*>(x), core0, core1, core2);
    k_gemm<<<dim3(SZ / BN, MTOT / BM), NTHR, SM_TOTAL>>>(bias, out);
}

// round 9
// speedup vs baseline: 1.2656x; 1.2656x over previous
#include <cuda_runtime.h>
#include <cuda_fp16.h>
#include <cstdint>

#define SZ    4096
#define MTOT  8192
#define BM    128
#define BN    256
#define BK    64
#define KIT   (SZ / BK)          // 64 k-steps
#define NTHR  512                // 16 warps: 4m x 4n, warp tile 32x64
#define NSTG  4                  // cp.async pipeline stages

// device scratch (no allocation allowed in kernel_launch)
__device__ __half g_Xh[(size_t)MTOT * SZ];   // x in fp16, row-major [M][K]
__device__ __half g_Gt[(size_t)SZ * SZ];     // Gt[n][k] = G[k][n], fp16, K-major

// ---------------------------------------------------------------------------
// helpers (base-PTX only: cp.async / ldmatrix / mma.sync)
// ---------------------------------------------------------------------------
__device__ __forceinline__ uint32_t smem_u32(const void* p) {
    uint32_t a;
    asm("{ .reg .u64 t; cvta.to.shared.u64 t, %1; cvt.u32.u64 %0, t; }"
        : "=r"(a) : "l"(p));
    return a;
}
__device__ __forceinline__ uint32_t swz128(uint32_t off) {
    return off ^ ((off >> 3) & 0x70);        // SW128: conflict-free 128B-row tiles
}
__device__ __forceinline__ void cp16(uint32_t sdst, const void* gsrc) {
    asm volatile("cp.async.cg.shared.global [%0], [%1], 16;" :: "r"(sdst), "l"(gsrc));
}
__device__ __forceinline__ void ldsm_x4(uint32_t& r0, uint32_t& r1, uint32_t& r2,
                                        uint32_t& r3, uint32_t addr) {
    asm volatile("ldmatrix.sync.aligned.m8n8.x4.shared.b16 {%0,%1,%2,%3}, [%4];"
                 : "=r"(r0), "=r"(r1), "=r"(r2), "=r"(r3) : "r"(addr));
}
__device__ __forceinline__ void mma16816(float* c, uint32_t a0, uint32_t a1,
                                         uint32_t a2, uint32_t a3,
                                         uint32_t b0, uint32_t b1) {
    asm volatile(
        "mma.sync.aligned.m16n8k16.row.col.f32.f16.f16.f32 "
        "{%0,%1,%2,%3}, {%4,%5,%6,%7}, {%8,%9}, {%0,%1,%2,%3};"
        : "+f"(c[0]), "+f"(c[1]), "+f"(c[2]), "+f"(c[3])
        : "r"(a0), "r"(a1), "r"(a2), "r"(a3), "r"(b0), "r"(b1));
}

// ---------------------------------------------------------------------------
// Kernel 1: x fp32 -> fp16  (separate kernel: 16 regs, full occupancy.
// Fusing with build_gt inflated regs to ~100 and made this latency-bound.)
// ---------------------------------------------------------------------------
__global__ void k_convert_x(const float4* __restrict__ x) {
    size_t i = (size_t)blockIdx.x * blockDim.x + threadIdx.x;   // over float4
    float4 v = x[i];
    __half2* o = reinterpret_cast<__half2*>(g_Xh) + 2 * i;
    o[0] = __floats2half2_rn(v.x, v.y);
    o[1] = __floats2half2_rn(v.z, v.w);
}

// ---------------------------------------------------------------------------
// Kernel 2: build Gt[n][k] = G[k][n] in fp16.
// ---------------------------------------------------------------------------
__global__ void __launch_bounds__(256)
k_build_gt(const float* __restrict__ core0, const float* __restrict__ core1,
           const float* __restrict__ core2) {
    const int x1 = blockIdx.y;
    const int k  = blockIdx.x * 256 + threadIdx.x;

    float c1r[64];  // C1[k, x1, c, b]
    const float4* c1p = reinterpret_cast<const float4*>(core1 + ((size_t)k * 16 + x1) * 64);
#pragma unroll
    for (int i = 0; i < 16; i++) {
        float4 v = c1p[i];
        c1r[4 * i] = v.x; c1r[4 * i + 1] = v.y; c1r[4 * i + 2] = v.z; c1r[4 * i + 3] = v.w;
    }
#pragma unroll
    for (int yc = 0; yc < 4; yc++) {
        float M[4][8];
#pragma unroll
        for (int yy = 0; yy < 4; yy++) {
            const int y = yc * 4 + yy;
            const float4* gp = reinterpret_cast<const float4*>(core0 + ((size_t)k * 16 + y) * 8);
            float4 a = gp[0], b = gp[1];
            float g0[8] = {a.x, a.y, a.z, a.w, b.x, b.y, b.z, b.w};
#pragma unroll
            for (int c = 0; c < 8; c++) {
                float s = 0.f;
#pragma unroll
                for (int bb = 0; bb < 8; bb++) s = fmaf(c1r[c * 8 + bb], g0[bb], s);
                M[yy][c] = s;
            }
        }
#pragma unroll
        for (int x2 = 0; x2 < 16; x2++) {
            const float4* cp = reinterpret_cast<const float4*>(core2 + ((size_t)k * 16 + x2) * 8);
            float4 a = cp[0], b = cp[1];
            float c2v[8] = {a.x, a.y, a.z, a.w, b.x, b.y, b.z, b.w};
#pragma unroll
            for (int yy = 0; yy < 4; yy++) {
                float s = 0.f;
#pragma unroll
                for (int c = 0; c < 8; c++) s = fmaf(c2v[c], M[yy][c], s);
                const int n = (yc * 4 + yy) * 256 + x1 * 16 + x2;
                g_Gt[(size_t)n * SZ + k] = __float2half_rn(s);
            }
        }
    }
}

// ---------------------------------------------------------------------------
// Kernel 3: GEMM out[m][n] = sum_k Xh[m][k] * Gt[n][k] + bias[n]
// 16 warps (4 warps/SMSP for latency hiding), warp grid 4m x 4n, tile 32x64.
// 4-stage cp.async pipeline (prefetch distance 3, wait_group 2).
// ---------------------------------------------------------------------------
#define A_BYTES  (BM * BK * 2)                    // 16384 per stage
#define B_BYTES  (BN * BK * 2)                    // 32768 per stage
#define SM_A     0
#define SM_B     (NSTG * A_BYTES)                 // 65536
#define SM_BIAS  (SM_B + NSTG * B_BYTES)          // 196608
#define SM_TOTAL (SM_BIAS + BN * 4)               // 197632

__global__ void __launch_bounds__(NTHR, 1)
k_gemm(const float* __restrict__ bias, float* __restrict__ out) {
    extern __shared__ char smem[];
    const uint32_t sb = smem_u32(smem);
    const int tid  = threadIdx.x;
    const int lane = tid & 31;
    const int wid  = tid >> 5;
    const int wm   = wid & 3;            // 4 m-warps x 32 rows
    const int wn   = wid >> 2;           // 4 n-warps x 64 cols
    const int m0 = blockIdx.y * BM;
    const int n0 = blockIdx.x * BN;

    float* sbias = reinterpret_cast<float*>(smem + SM_BIAS);
    if (tid < BN) sbias[tid] = bias[n0 + tid];

    // ---- loader: one full (A,B) k-stage; 512 threads, 16B per cp ----
    const int chunk = tid & 7;           // 16B chunk within 128B row
    const int rbase = tid >> 3;          // 0..63
    auto load_stage = [&](int ks, int stage) {
        const int k0 = ks * BK;
        const uint32_t ab = sb + SM_A + stage * A_BYTES;
        const uint32_t bb = sb + SM_B + stage * B_BYTES;
        const __half* ag = g_Xh + (size_t)(m0 + rbase) * SZ + k0 + chunk * 8;
        const __half* bg = g_Gt + (size_t)(n0 + rbase) * SZ + k0 + chunk * 8;
#pragma unroll
        for (int it = 0; it < 2; it++) {   // A: 128 rows
            const int r = rbase + 64 * it;
            cp16(ab + swz128((uint32_t)(r * 128 + chunk * 16)), ag + (size_t)(64 * it) * SZ);
        }
#pragma unroll
        for (int it = 0; it < 4; it++) {   // B: 256 rows
            const int r = rbase + 64 * it;
            cp16(bb + swz128((uint32_t)(r * 128 + chunk * 16)), bg + (size_t)(64 * it) * SZ);
        }
        asm volatile("cp.async.commit_group;" ::: "memory");
    };

    float acc[2][8][4];
#pragma unroll
    for (int mt = 0; mt < 2; mt++)
#pragma unroll
        for (int nt = 0; nt < 8; nt++)
#pragma unroll
            for (int j = 0; j < 4; j++) acc[mt][nt][j] = 0.f;

    load_stage(0, 0);
    load_stage(1, 1);
    load_stage(2, 2);

    // lane pieces for ldmatrix addressing
    const int g = lane >> 3;                                   // 0..3
    const int arow_off = ((lane >> 3) & 1) * 8 + (lane & 7);   // A row within 16
    const int acol_off = (lane >> 4) << 4;                     // A col byte (0/16)
    const int brow_off = ((g & 2) << 2) + (lane & 7);          // B row within 16
    const int bcol_off = (g & 1) << 4;                         // B col byte (0/16)

    for (int ks = 0; ks < KIT; ks++) {
        asm volatile("cp.async.wait_group 2;" ::: "memory");
        __syncthreads();
        if (ks + 3 < KIT) load_stage(ks + 3, (ks + 3) % NSTG);
        else              asm volatile("cp.async.commit_group;" ::: "memory");

        const uint32_t ab = sb + SM_A + (ks % NSTG) * A_BYTES;
        const uint32_t bb = sb + SM_B + (ks % NSTG) * B_BYTES;
#pragma unroll
        for (int k16 = 0; k16 < 4; k16++) {
            uint32_t a[2][4];
#pragma unroll
            for (int mt = 0; mt < 2; mt++) {
                const int row = wm * 32 + mt * 16 + arow_off;
                const int colb = k16 * 32 + acol_off;
                ldsm_x4(a[mt][0], a[mt][1], a[mt][2], a[mt][3],
                        ab + swz128((uint32_t)(row * 128 + colb)));
            }
            uint32_t b[8][2];
#pragma unroll
            for (int np = 0; np < 4; np++) {
                const int row = wn * 64 + np * 16 + brow_off;
                const int colb = k16 * 32 + bcol_off;
                uint32_t r0, r1, r2, r3;
                ldsm_x4(r0, r1, r2, r3, bb + swz128((uint32_t)(row * 128 + colb)));
                b[2 * np][0] = r0; b[2 * np][1] = r1;
                b[2 * np + 1][0] = r2; b[2 * np + 1][1] = r3;
            }
#pragma unroll
            for (int mt = 0; mt < 2; mt++)
#pragma unroll
                for (int nt = 0; nt < 8; nt++)
                    mma16816(acc[mt][nt], a[mt][0], a[mt][1], a[mt][2], a[mt][3],
                             b[nt][0], b[nt][1]);
        }
    }

    // ---- epilogue ----
    const int crow = lane >> 2;
    const int ccol = (lane & 3) * 2;
#pragma unroll
    for (int mt = 0; mt < 2; mt++) {
        const int m = m0 + wm * 32 + mt * 16 + crow;
#pragma unroll
        for (int nt = 0; nt < 8; nt++) {
            const int nc = wn * 64 + nt * 8 + ccol;
            float2 v0, v1;
            v0.x = acc[mt][nt][0] + sbias[nc];
            v0.y = acc[mt][nt][1] + sbias[nc + 1];
            v1.x = acc[mt][nt][2] + sbias[nc];
            v1.y = acc[mt][nt][3] + sbias[nc + 1];
            *reinterpret_cast<float2*>(out + (size_t)m * SZ + n0 + nc)       = v0;
            *reinterpret_cast<float2*>(out + (size_t)(m + 8) * SZ + n0 + nc) = v1;
        }
    }
}

// ---------------------------------------------------------------------------
extern "C" void kernel_launch(void* const* d_in, const int* in_sizes, int n_in,
                              void* d_out, int out_size) {
    const float* x     = (const float*)d_in[0];
    const float* core0 = (const float*)d_in[1];
    const float* core1 = (const float*)d_in[2];
    const float* core2 = (const float*)d_in[3];
    const float* bias  = (const float*)d_in[4];
    float* out = (float*)d_out;

    static bool attr_set = false;
    if (!attr_set) {
        cudaFuncSetAttribute(k_gemm, cudaFuncAttributeMaxDynamicSharedMemorySize, SM_TOTAL);
        attr_set = true;
    }

    k_convert_x<<<(int)((size_t)MTOT * SZ / 4 / 256), 256>>>(
        reinterpret_cast<const float4*>(x));
    k_build_gt<<<dim3(16, 16), 256>>>(core0, core1, core2);
    k_gemm<<<dim3(SZ / BN, MTOT / BM), NTHR, SM_TOTAL>>>(bias, out);
}

// round 10
// speedup vs baseline: 1.2775x; 1.0094x over previous
#include <cuda_runtime.h>
#include <cuda_fp16.h>
#include <cstdint>

#define SZ    4096
#define MTOT  8192
#define BM    128
#define BN    128
#define BK    64
#define KIT   (SZ / BK)          // 64 k-steps
#define NTHR  128                // 4 warps: 2m x 2n, warp tile 64x64
#define NSTG  3                  // cp.async stages (96KB -> 2 CTAs/SM)

// device scratch (no allocation allowed in kernel_launch)
__device__ __half g_Xh[(size_t)MTOT * SZ];   // x in fp16, row-major [M][K]
__device__ __half g_Gt[(size_t)SZ * SZ];     // Gt[n][k] = G[k][n], fp16, K-major

// ---------------------------------------------------------------------------
// helpers (base-PTX only: cp.async / ldmatrix / mma.sync)
// ---------------------------------------------------------------------------
__device__ __forceinline__ uint32_t smem_u32(const void* p) {
    uint32_t a;
    asm("{ .reg .u64 t; cvta.to.shared.u64 t, %1; cvt.u32.u64 %0, t; }"
        : "=r"(a) : "l"(p));
    return a;
}
__device__ __forceinline__ uint32_t swz128(uint32_t off) {
    return off ^ ((off >> 3) & 0x70);        // SW128: conflict-free 128B-row tiles
}
__device__ __forceinline__ void cp16(uint32_t sdst, const void* gsrc) {
    asm volatile("cp.async.cg.shared.global [%0], [%1], 16;" :: "r"(sdst), "l"(gsrc));
}
__device__ __forceinline__ void ldsm_x4(uint32_t& r0, uint32_t& r1, uint32_t& r2,
                                        uint32_t& r3, uint32_t addr) {
    asm volatile("ldmatrix.sync.aligned.m8n8.x4.shared.b16 {%0,%1,%2,%3}, [%4];"
                 : "=r"(r0), "=r"(r1), "=r"(r2), "=r"(r3) : "r"(addr));
}
__device__ __forceinline__ void mma16816(float* c, uint32_t a0, uint32_t a1,
                                         uint32_t a2, uint32_t a3,
                                         uint32_t b0, uint32_t b1) {
    asm volatile(
        "mma.sync.aligned.m16n8k16.row.col.f32.f16.f16.f32 "
        "{%0,%1,%2,%3}, {%4,%5,%6,%7}, {%8,%9}, {%0,%1,%2,%3};"
        : "+f"(c[0]), "+f"(c[1]), "+f"(c[2]), "+f"(c[3])
        : "r"(a0), "r"(a1), "r"(a2), "r"(a3), "r"(b0), "r"(b1));
}

// ---------------------------------------------------------------------------
// Kernel 1: x fp32 -> fp16 (separate: 16 regs, full occupancy)
// ---------------------------------------------------------------------------
__global__ void k_convert_x(const float4* __restrict__ x) {
    size_t i = (size_t)blockIdx.x * blockDim.x + threadIdx.x;   // over float4
    float4 v = x[i];
    __half2* o = reinterpret_cast<__half2*>(g_Xh) + 2 * i;
    o[0] = __floats2half2_rn(v.x, v.y);
    o[1] = __floats2half2_rn(v.z, v.w);
}

// ---------------------------------------------------------------------------
// Kernel 2: build Gt[n][k] = G[k][n] in fp16.
// ---------------------------------------------------------------------------
__global__ void __launch_bounds__(256)
k_build_gt(const float* __restrict__ core0, const float* __restrict__ core1,
           const float* __restrict__ core2) {
    const int x1 = blockIdx.y;
    const int k  = blockIdx.x * 256 + threadIdx.x;

    float c1r[64];  // C1[k, x1, c, b]
    const float4* c1p = reinterpret_cast<const float4*>(core1 + ((size_t)k * 16 + x1) * 64);
#pragma unroll
    for (int i = 0; i < 16; i++) {
        float4 v = c1p[i];
        c1r[4 * i] = v.x; c1r[4 * i + 1] = v.y; c1r[4 * i + 2] = v.z; c1r[4 * i + 3] = v.w;
    }
#pragma unroll
    for (int yc = 0; yc < 4; yc++) {
        float M[4][8];
#pragma unroll
        for (int yy = 0; yy < 4; yy++) {
            const int y = yc * 4 + yy;
            const float4* gp = reinterpret_cast<const float4*>(core0 + ((size_t)k * 16 + y) * 8);
            float4 a = gp[0], b = gp[1];
            float g0[8] = {a.x, a.y, a.z, a.w, b.x, b.y, b.z, b.w};
#pragma unroll
            for (int c = 0; c < 8; c++) {
                float s = 0.f;
#pragma unroll
                for (int bb = 0; bb < 8; bb++) s = fmaf(c1r[c * 8 + bb], g0[bb], s);
                M[yy][c] = s;
            }
        }
#pragma unroll
        for (int x2 = 0; x2 < 16; x2++) {
            const float4* cp = reinterpret_cast<const float4*>(core2 + ((size_t)k * 16 + x2) * 8);
            float4 a = cp[0], b = cp[1];
            float c2v[8] = {a.x, a.y, a.z, a.w, b.x, b.y, b.z, b.w};
#pragma unroll
            for (int yy = 0; yy < 4; yy++) {
                float s = 0.f;
#pragma unroll
                for (int c = 0; c < 8; c++) s = fmaf(c2v[c], M[yy][c], s);
                const int n = (yc * 4 + yy) * 256 + x1 * 16 + x2;
                g_Gt[(size_t)n * SZ + k] = __float2half_rn(s);
            }
        }
    }
}

// ---------------------------------------------------------------------------
// Kernel 3: GEMM out[m][n] = sum_k Xh[m][k] * Gt[n][k] + bias[n]
// 2 CTAs/SM (smem-limited): two independent barrier domains so one CTA's
// wait_group/__syncthreads bubble is covered by the other CTA's MMA stream.
// 4 warps (2m x 2n), warp tile 64x64 -> minimal crossbar bytes per MAC.
// ---------------------------------------------------------------------------
#define A_BYTES  (BM * BK * 2)                    // 16384 per stage
#define B_BYTES  (BN * BK * 2)                    // 16384 per stage
#define SM_A     0
#define SM_B     (NSTG * A_BYTES)                 // 49152
#define SM_BIAS  (SM_B + NSTG * B_BYTES)          // 98304
#define SM_TOTAL (SM_BIAS + BN * 4)               // 98816  (x2 CTAs = 193KB)

__global__ void __launch_bounds__(NTHR, 2)
k_gemm(const float* __restrict__ bias, float* __restrict__ out) {
    extern __shared__ char smem[];
    const uint32_t sb = smem_u32(smem);
    const int tid  = threadIdx.x;
    const int lane = tid & 31;
    const int wid  = tid >> 5;
    const int wm   = wid & 1;            // 2 m-warps x 64 rows
    const int wn   = wid >> 1;           // 2 n-warps x 64 cols
    const int m0 = blockIdx.y * BM;
    const int n0 = blockIdx.x * BN;

    float* sbias = reinterpret_cast<float*>(smem + SM_BIAS);
    sbias[tid] = bias[n0 + tid];

    // ---- loader: one full (A,B) k-stage; 128 threads, 16B per cp ----
    const int chunk = tid & 7;           // 16B chunk within 128B row
    const int rbase = tid >> 3;          // 0..15
    auto load_stage = [&](int ks, int stage) {
        const int k0 = ks * BK;
        const uint32_t ab = sb + SM_A + stage * A_BYTES;
        const uint32_t bb = sb + SM_B + stage * B_BYTES;
        const __half* ag = g_Xh + (size_t)(m0 + rbase) * SZ + k0 + chunk * 8;
        const __half* bg = g_Gt + (size_t)(n0 + rbase) * SZ + k0 + chunk * 8;
#pragma unroll
        for (int it = 0; it < 8; it++) {   // A: 128 rows
            const int r = rbase + 16 * it;
            cp16(ab + swz128((uint32_t)(r * 128 + chunk * 16)), ag + (size_t)(16 * it) * SZ);
        }
#pragma unroll
        for (int it = 0; it < 8; it++) {   // B: 128 rows
            const int r = rbase + 16 * it;
            cp16(bb + swz128((uint32_t)(r * 128 + chunk * 16)), bg + (size_t)(16 * it) * SZ);
        }
        asm volatile("cp.async.commit_group;" ::: "memory");
    };

    float acc[4][8][4];
#pragma unroll
    for (int mt = 0; mt < 4; mt++)
#pragma unroll
        for (int nt = 0; nt < 8; nt++)
#pragma unroll
            for (int j = 0; j < 4; j++) acc[mt][nt][j] = 0.f;

    load_stage(0, 0);
    load_stage(1, 1);

    // lane pieces for ldmatrix addressing
    const int g = lane >> 3;                                   // 0..3
    const int arow_off = ((lane >> 3) & 1) * 8 + (lane & 7);   // A row within 16
    const int acol_off = (lane >> 4) << 4;                     // A col byte (0/16)
    const int brow_off = ((g & 2) << 2) + (lane & 7);          // B row within 16
    const int bcol_off = (g & 1) << 4;                         // B col byte (0/16)

    for (int ks = 0; ks < KIT; ks++) {
        asm volatile("cp.async.wait_group 1;" ::: "memory");
        __syncthreads();
        if (ks + 2 < KIT) load_stage(ks + 2, (ks + 2) % NSTG);
        else              asm volatile("cp.async.commit_group;" ::: "memory");

        const uint32_t ab = sb + SM_A + (ks % NSTG) * A_BYTES;
        const uint32_t bb = sb + SM_B + (ks % NSTG) * B_BYTES;
#pragma unroll
        for (int k16 = 0; k16 < 4; k16++) {
            uint32_t a[4][4];
#pragma unroll
            for (int mt = 0; mt < 4; mt++) {
                const int row = wm * 64 + mt * 16 + arow_off;
                const int colb = k16 * 32 + acol_off;
                ldsm_x4(a[mt][0], a[mt][1], a[mt][2], a[mt][3],
                        ab + swz128((uint32_t)(row * 128 + colb)));
            }
            uint32_t b[8][2];
#pragma unroll
            for (int np = 0; np < 4; np++) {
                const int row = wn * 64 + np * 16 + brow_off;
                const int colb = k16 * 32 + bcol_off;
                uint32_t r0, r1, r2, r3;
                ldsm_x4(r0, r1, r2, r3, bb + swz128((uint32_t)(row * 128 + colb)));
                b[2 * np][0] = r0; b[2 * np][1] = r1;
                b[2 * np + 1][0] = r2; b[2 * np + 1][1] = r3;
            }
#pragma unroll
            for (int mt = 0; mt < 4; mt++)
#pragma unroll
                for (int nt = 0; nt < 8; nt++)
                    mma16816(acc[mt][nt], a[mt][0], a[mt][1], a[mt][2], a[mt][3],
                             b[nt][0], b[nt][1]);
        }
    }

    // ---- epilogue ----
    const int crow = lane >> 2;
    const int ccol = (lane & 3) * 2;
#pragma unroll
    for (int mt = 0; mt < 4; mt++) {
        const int m = m0 + wm * 64 + mt * 16 + crow;
#pragma unroll
        for (int nt = 0; nt < 8; nt++) {
            const int nc = wn * 64 + nt * 8 + ccol;
            float2 v0, v1;
            v0.x = acc[mt][nt][0] + sbias[nc];
            v0.y = acc[mt][nt][1] + sbias[nc + 1];
            v1.x = acc[mt][nt][2] + sbias[nc];
            v1.y = acc[mt][nt][3] + sbias[nc + 1];
            *reinterpret_cast<float2*>(out + (size_t)m * SZ + n0 + nc)       = v0;
            *reinterpret_cast<float2*>(out + (size_t)(m + 8) * SZ + n0 + nc) = v1;
        }
    }
}

// ---------------------------------------------------------------------------
extern "C" void kernel_launch(void* const* d_in, const int* in_sizes, int n_in,
                              void* d_out, int out_size) {
    const float* x     = (const float*)d_in[0];
    const float* core0 = (const float*)d_in[1];
    const float* core1 = (const float*)d_in[2];
    const float* core2 = (const float*)d_in[3];
    const float* bias  = (const float*)d_in[4];
    float* out = (float*)d_out;

    static bool attr_set = false;
    if (!attr_set) {
        cudaFuncSetAttribute(k_gemm, cudaFuncAttributeMaxDynamicSharedMemorySize, SM_TOTAL);
        attr_set = true;
    }

    k_convert_x<<<(int)((size_t)MTOT * SZ / 4 / 256), 256>>>(
        reinterpret_cast<const float4*>(x));
    k_build_gt<<<dim3(16, 16), 256>>>(core0, core1, core2);
    k_gemm<<<dim3(SZ / BN, MTOT / BM), NTHR, SM_TOTAL>>>(bias, out);
}